// round 4
// baseline (speedup 1.0000x reference)
#include <cuda_runtime.h>
#include <cstdint>

#define NN 50000
#define EE 800000
#define GG 64
#define FF 64
#define BN_EPS 1e-5f

// ---------------- scratch (static device globals) ---------------------------
__device__ float d_h[(size_t)NN * FF];     // GEMM output / gather source
__device__ float d_y[(size_t)NN * FF];     // gather output / GEMM input
__device__ float d_s[NN];                  // layer-1 scalar aggregate
__device__ float d_dinv[NN];
__device__ int   d_cnt_in[NN];             // in-degree (excl self-loop)
__device__ int   d_ptr[NN + 1];            // CSR row pointers (by col/dst)
__device__ int   d_pos[NN];                // fill cursors
__device__ int2  d_csr[EE];                // {src, bitcast(norm)}
__device__ float d_ssum[2];                // scalar sum / sumsq (layer 1)
__device__ float d_fsum[3][FF];            // per-feature sums, layers 2..4
__device__ float d_fsq[3][FF];
__device__ float d_pooled[GG * FF];
__device__ float d_cnt[GG];
__device__ float d_aff_a[4][FF];           // fused BN affine: z = relu(a*y + c)
__device__ float d_aff_c[4][FF];

// ---------------- setup ------------------------------------------------------
__global__ void k_zero() {
    int t = blockIdx.x * blockDim.x + threadIdx.x;
    if (t < NN) d_cnt_in[t] = 0;
    if (t < 2) d_ssum[t] = 0.f;
    if (t < 3 * FF) { ((float*)d_fsum)[t] = 0.f; ((float*)d_fsq)[t] = 0.f; }
    if (t < GG * FF) d_pooled[t] = 0.f;
    if (t < GG) d_cnt[t] = 0.f;
}

__global__ void k_count(const int* __restrict__ ei, int E_) {
    int e = blockIdx.x * blockDim.x + threadIdx.x;
    if (e < E_) atomicAdd(&d_cnt_in[ei[E_ + e]], 1);
}

// single-block exclusive scan of d_cnt_in -> d_ptr, d_pos
__global__ void k_scan() {
    __shared__ int sums[1024];
    int t = threadIdx.x;
    const int CH = (NN + 1023) / 1024;   // 49
    int start = t * CH;
    int end = start + CH; if (end > NN) end = NN;
    int s = 0;
    for (int i = start; i < end; i++) s += d_cnt_in[i];
    sums[t] = s;
    __syncthreads();
    for (int off = 1; off < 1024; off <<= 1) {
        int v = (t >= off) ? sums[t - off] : 0;
        __syncthreads();
        sums[t] += v;
        __syncthreads();
    }
    int excl = (t == 0) ? 0 : sums[t - 1];
    for (int i = start; i < end; i++) {
        d_ptr[i] = excl;
        d_pos[i] = excl;
        excl += d_cnt_in[i];
    }
    if (t == 1023) d_ptr[NN] = excl;
}

__global__ void k_dinv() {
    int n = blockIdx.x * blockDim.x + threadIdx.x;
    if (n < NN) d_dinv[n] = rsqrtf((float)d_cnt_in[n] + 1.0f);  // +1 self-loop
}

__global__ void k_fill(const int* __restrict__ ei, int E_) {
    int e = blockIdx.x * blockDim.x + threadIdx.x;
    if (e >= E_) return;
    int r = ei[e], c = ei[E_ + e];
    float nm = d_dinv[r] * d_dinv[c];
    int p = atomicAdd(&d_pos[c], 1);
    d_csr[p] = make_int2(r, __float_as_int(nm));
}

// ---------------- layer 1: scalar gather + fused stats ----------------------
__global__ void k_gather1(const float* __restrict__ x) {
    int n = blockIdx.x * blockDim.x + threadIdx.x;
    float s = 0.f;
    if (n < NN) {
        int b = d_ptr[n], en = d_ptr[n + 1];
        for (int p = b; p < en; p++) {
            int2 v = __ldg(&d_csr[p]);
            s = fmaf(__ldg(&x[v.x]), __int_as_float(v.y), s);
        }
        float di = d_dinv[n];
        s = fmaf(x[n], di * di, s);
        d_s[n] = s;
    }
    float q = s * s;
    for (int o = 16; o; o >>= 1) {
        s += __shfl_down_sync(0xffffffffu, s, o);
        q += __shfl_down_sync(0xffffffffu, q, o);
    }
    __shared__ float sh[2][8];
    int w = threadIdx.x >> 5;
    if ((threadIdx.x & 31) == 0) { sh[0][w] = s; sh[1][w] = q; }
    __syncthreads();
    if (threadIdx.x == 0) {
        s = 0.f; q = 0.f;
        for (int i = 0; i < 8; i++) { s += sh[0][i]; q += sh[1][i]; }
        atomicAdd(&d_ssum[0], s);
        atomicAdd(&d_ssum[1], q);
    }
}

__global__ void k_fin1(const float* __restrict__ W1, const float* __restrict__ g1,
                       const float* __restrict__ bt1) {
    int f = threadIdx.x;
    if (f >= FF) return;
    float inv_n = 1.0f / (float)NN;
    float mean_s = d_ssum[0] * inv_n;
    float var_s  = d_ssum[1] * inv_n - mean_s * mean_s;
    float w = W1[f];
    float ia = g1[f] * rsqrtf(var_s * w * w + BN_EPS);
    float A = ia * w;
    d_aff_a[0][f] = A;
    d_aff_c[0][f] = bt1[f] - A * mean_s;
}

__global__ void k_fin64(int L, const float* __restrict__ g, const float* __restrict__ bt) {
    int f = threadIdx.x;
    if (f >= FF) return;
    float inv_n = 1.0f / (float)NN;
    float mean = d_fsum[L][f] * inv_n;
    float var  = d_fsq[L][f] * inv_n - mean * mean;
    float ia = g[f] * rsqrtf(var + BN_EPS);
    d_aff_a[L + 1][f] = ia;
    d_aff_c[L + 1][f] = bt[f] - ia * mean;
}

// ---------------- GEMM: d_h = relu(affine(src)) @ W -------------------------
template <bool FROM_S>
__global__ void k_gemm(int L, const float* __restrict__ W) {
    __shared__ float Zs[FF][FF + 1];   // [k][localrow]
    __shared__ float Ws[FF][FF];       // [k][col]
    __shared__ float sa[FF], sc[FF];
    int t = threadIdx.x;
    int base = blockIdx.x * FF;

    if (t < FF) { sa[t] = d_aff_a[L][t]; sc[t] = d_aff_c[L][t]; }
    __syncthreads();

    {
        const float4* W4 = (const float4*)W;
        float4* Ws4 = (float4*)&Ws[0][0];
        #pragma unroll
        for (int i = 0; i < 4; i++) Ws4[t + i * 256] = W4[t + i * 256];
    }

    int lr = t >> 2;
    int cg = (t & 3) * 4;
    int row = base + lr;
    if (FROM_S) {
        float sval = (row < NN) ? d_s[row] : 0.f;
        #pragma unroll
        for (int i = 0; i < 4; i++) {
            int cc = cg + i * 16;
            #pragma unroll
            for (int j = 0; j < 4; j++)
                Zs[cc + j][lr] = fmaxf(sa[cc + j] * sval + sc[cc + j], 0.f);
        }
    } else {
        #pragma unroll
        for (int i = 0; i < 4; i++) {
            int cc = cg + i * 16;
            float4 v = (row < NN) ? *(const float4*)(d_y + (size_t)row * FF + cc)
                                  : make_float4(0.f, 0.f, 0.f, 0.f);
            Zs[cc + 0][lr] = fmaxf(sa[cc + 0] * v.x + sc[cc + 0], 0.f);
            Zs[cc + 1][lr] = fmaxf(sa[cc + 1] * v.y + sc[cc + 1], 0.f);
            Zs[cc + 2][lr] = fmaxf(sa[cc + 2] * v.z + sc[cc + 2], 0.f);
            Zs[cc + 3][lr] = fmaxf(sa[cc + 3] * v.w + sc[cc + 3], 0.f);
        }
    }
    __syncthreads();

    int tx = t & 15, ty = t >> 4;
    float acc[4][4] = {};
    #pragma unroll 16
    for (int k = 0; k < FF; k++) {
        float zr[4], wc[4];
        #pragma unroll
        for (int r = 0; r < 4; r++) zr[r] = Zs[k][ty + 16 * r];
        #pragma unroll
        for (int j = 0; j < 4; j++) wc[j] = Ws[k][tx + 16 * j];
        #pragma unroll
        for (int r = 0; r < 4; r++)
            #pragma unroll
            for (int j = 0; j < 4; j++)
                acc[r][j] = fmaf(zr[r], wc[j], acc[r][j]);
    }
    #pragma unroll
    for (int r = 0; r < 4; r++) {
        int orow = base + ty + 16 * r;
        if (orow < NN) {
            #pragma unroll
            for (int j = 0; j < 4; j++)
                d_h[(size_t)orow * FF + tx + 16 * j] = acc[r][j];
        }
    }
}

// ---------------- 64-wide gather: warp per node, fused stats -----------------
// lane l owns features {2l, 2l+1}. Grid-stride over nodes; per-warp register
// stats partials, reduced via smem + one global atomic per feature per block.
__global__ void k_gather64(int L) {
    __shared__ float smS[8][128];
    __shared__ float smQ[8][128];
    int t = threadIdx.x;
    int lane = t & 31, w = t >> 5;          // 8 warps / block
    float2 rS = make_float2(0.f, 0.f);
    float2 rQ = make_float2(0.f, 0.f);

    for (int n = blockIdx.x * 8 + w; n < NN; n += gridDim.x * 8) {
        int b = d_ptr[n], en = d_ptr[n + 1];
        float2 acc = make_float2(0.f, 0.f);
        const float2* hbase = (const float2*)d_h;
        int p = b;
        // 2-deep unroll for load-level parallelism on the dependent chain
        for (; p + 1 < en; p += 2) {
            int2 v0 = __ldg(&d_csr[p]);
            int2 v1 = __ldg(&d_csr[p + 1]);
            float2 h0 = __ldg(hbase + (size_t)v0.x * 32 + lane);
            float2 h1 = __ldg(hbase + (size_t)v1.x * 32 + lane);
            float n0 = __int_as_float(v0.y), n1 = __int_as_float(v1.y);
            acc.x = fmaf(h0.x, n0, acc.x); acc.y = fmaf(h0.y, n0, acc.y);
            acc.x = fmaf(h1.x, n1, acc.x); acc.y = fmaf(h1.y, n1, acc.y);
        }
        if (p < en) {
            int2 v0 = __ldg(&d_csr[p]);
            float2 h0 = __ldg(hbase + (size_t)v0.x * 32 + lane);
            float n0 = __int_as_float(v0.y);
            acc.x = fmaf(h0.x, n0, acc.x); acc.y = fmaf(h0.y, n0, acc.y);
        }
        // self-loop
        float di = d_dinv[n]; float d2 = di * di;
        float2 hs = __ldg(hbase + (size_t)n * 32 + lane);
        acc.x = fmaf(hs.x, d2, acc.x); acc.y = fmaf(hs.y, d2, acc.y);
        *(float2*)(d_y + (size_t)n * FF + 2 * lane) = acc;
        // stats partials
        rS.x += acc.x; rS.y += acc.y;
        rQ.x = fmaf(acc.x, acc.x, rQ.x); rQ.y = fmaf(acc.y, acc.y, rQ.y);
    }
    smS[w][2 * lane] = rS.x; smS[w][2 * lane + 1] = rS.y;
    smQ[w][2 * lane] = rQ.x; smQ[w][2 * lane + 1] = rQ.y;
    __syncthreads();
    if (t < 128) {
        float s = 0.f, q = 0.f;
        #pragma unroll
        for (int i = 0; i < 8; i++) { s += smS[i][t]; q += smQ[i][t]; }
        // features 0..63 map to t in [0,64) pairs? No: t indexes 128 slots,
        // slot = feature when FF=64? slots 0..127 but FF=64 -> slot t covers
        // feature t for t<64 and t-? -- lanes write 2*lane in [0,64). So only
        // slots [0,64) are used.
        if (t < FF) {
            atomicAdd(&d_fsum[L][t], s);
            atomicAdd(&d_fsq[L][t], q);
        }
    }
}

// ---------------- pooling + head ---------------------------------------------
__global__ void k_pool(const int* __restrict__ batch) {
    int t = threadIdx.x;
    int f = t & 63, rg = t >> 6;
    int base = blockIdx.x * 256;
    float af = d_aff_a[3][f], cf = d_aff_c[3][f];
    float acc = 0.f, cacc = 0.f;
    int gcur = -1;
    for (int i = 0; i < 64; i++) {
        int n = base + rg + 4 * i;
        if (n >= NN) break;
        int g = batch[n];
        if (g != gcur) {
            if (gcur >= 0) {
                atomicAdd(&d_pooled[gcur * FF + f], acc);
                if (f == 0) atomicAdd(&d_cnt[gcur], cacc);
            }
            gcur = g; acc = 0.f; cacc = 0.f;
        }
        float v = fmaxf(af * d_y[(size_t)n * FF + f] + cf, 0.f);
        acc += v; cacc += 1.f;
    }
    if (gcur >= 0) {
        atomicAdd(&d_pooled[gcur * FF + f], acc);
        if (f == 0) atomicAdd(&d_cnt[gcur], cacc);
    }
}

__global__ void k_fc(const float* __restrict__ fw1, const float* __restrict__ fb1,
                     const float* __restrict__ fw2, const float* __restrict__ fb2,
                     float* __restrict__ out) {
    __shared__ float P[GG][FF];
    __shared__ float H[GG][128];
    int t = threadIdx.x;   // 128 threads
    for (int i = t; i < GG * FF; i += 128) {
        int g = i >> 6;
        float cc = d_cnt[g]; cc = (cc < 1.f) ? 1.f : cc;
        P[g][i & 63] = d_pooled[i] / cc;
    }
    __syncthreads();
    int j = t;
    for (int g = 0; g < GG; g++) {
        float s = fb1[j];
        #pragma unroll 8
        for (int f = 0; f < FF; f++) s = fmaf(P[g][f], fw1[j * FF + f], s);
        H[g][j] = fmaxf(s, 0.f);
    }
    __syncthreads();
    for (int i = t; i < GG * 10; i += 128) {
        int g = i / 10, k = i % 10;
        float s = fb2[k];
        #pragma unroll 8
        for (int jj = 0; jj < 128; jj++) s = fmaf(H[g][jj], fw2[k * 128 + jj], s);
        out[i] = s;
    }
}

// ---------------- launch -----------------------------------------------------
extern "C" void kernel_launch(void* const* d_in, const int* in_sizes, int n_in,
                              void* d_out, int out_size) {
    const float* x   = (const float*)d_in[0];
    const int*   ei  = (const int*)d_in[1];
    const int*   bat = (const int*)d_in[2];
    const float* W1  = (const float*)d_in[3];
    const float* g1  = (const float*)d_in[5];
    const float* bt1 = (const float*)d_in[6];
    const float* W2  = (const float*)d_in[7];
    const float* g2  = (const float*)d_in[9];
    const float* bt2 = (const float*)d_in[10];
    const float* W3  = (const float*)d_in[11];
    const float* g3  = (const float*)d_in[13];
    const float* bt3 = (const float*)d_in[14];
    const float* W4  = (const float*)d_in[15];
    const float* g4  = (const float*)d_in[17];
    const float* bt4 = (const float*)d_in[18];
    const float* fw1 = (const float*)d_in[19];
    const float* fb1 = (const float*)d_in[20];
    const float* fw2 = (const float*)d_in[21];
    const float* fb2 = (const float*)d_in[22];
    float* out = (float*)d_out;

    int E_ = in_sizes[1] / 2;
    if (E_ > EE) E_ = EE;

    const int TB = 256;
    int nb_n = (NN + TB - 1) / TB;
    int nb_e = (E_ + TB - 1) / TB;
    int nb_g = (NN + 63) / 64;
    const int GATHER_BLKS = 400;    // 3200 warps

    // CSR build
    k_zero<<<nb_n, TB>>>();
    k_count<<<nb_e, TB>>>(ei, E_);
    k_scan<<<1, 1024>>>();
    k_dinv<<<nb_n, TB>>>();
    k_fill<<<nb_e, TB>>>(ei, E_);

    // layer 1 (scalar)
    k_gather1<<<nb_n, TB>>>(x);
    k_fin1<<<1, 64>>>(W1, g1, bt1);

    // layer 2
    k_gemm<true><<<nb_g, TB>>>(0, W2);
    k_gather64<<<GATHER_BLKS, TB>>>(0);
    k_fin64<<<1, 64>>>(0, g2, bt2);

    // layer 3
    k_gemm<false><<<nb_g, TB>>>(1, W3);
    k_gather64<<<GATHER_BLKS, TB>>>(1);
    k_fin64<<<1, 64>>>(1, g3, bt3);

    // layer 4
    k_gemm<false><<<nb_g, TB>>>(2, W4);
    k_gather64<<<GATHER_BLKS, TB>>>(2);
    k_fin64<<<1, 64>>>(2, g4, bt4);

    // pool + head
    k_pool<<<(NN + 255) / 256, TB>>>(bat);
    k_fc<<<1, 128>>>(fw1, fb1, fw2, fb2, out);
}

// round 5
// speedup vs baseline: 1.1334x; 1.1334x over previous
#include <cuda_runtime.h>
#include <cstdint>

#define NN 50000
#define EE 800000
#define GG 64
#define FF 64
#define BN_EPS 1e-5f

// ---------------- scratch (static device globals) ---------------------------
__device__ float d_h[(size_t)NN * FF];     // GEMM output / gather source
__device__ float d_y[(size_t)NN * FF];     // gather output / GEMM input
__device__ float d_s[NN];                  // layer-1 scalar aggregate
__device__ float d_dinv[NN];
__device__ int   d_cnt_in[NN];             // in-degree (incl self-loop)
__device__ int   d_ptr[NN + 1];            // CSR row pointers (by dst)
__device__ int   d_pos[NN];                // fill cursors
__device__ int2  d_csr[EE + NN];           // {src, bitcast(norm)}; self incl.
__device__ float d_ssum[2];                // scalar sum / sumsq (layer 1)
__device__ float d_fsum[3][FF];            // per-feature sums, layers 2..4
__device__ float d_fsq[3][FF];
__device__ float d_pooled[GG * FF];
__device__ float d_cnt[GG];

// ---------------- setup ------------------------------------------------------
__global__ void k_zero() {
    int t = blockIdx.x * blockDim.x + threadIdx.x;
    if (t < NN) d_cnt_in[t] = 1;           // self-loop pre-counted
    if (t < 2) d_ssum[t] = 0.f;
    if (t < 3 * FF) { ((float*)d_fsum)[t] = 0.f; ((float*)d_fsq)[t] = 0.f; }
    if (t < GG * FF) d_pooled[t] = 0.f;
    if (t < GG) d_cnt[t] = 0.f;
}

__global__ void k_count(const int* __restrict__ ei, int E_) {
    int e = blockIdx.x * blockDim.x + threadIdx.x;
    if (e < E_) atomicAdd(&d_cnt_in[ei[E_ + e]], 1);
}

// single-block exclusive scan of d_cnt_in -> d_ptr
__global__ void k_scan() {
    __shared__ int sums[1024];
    int t = threadIdx.x;
    const int CH = (NN + 1023) / 1024;   // 49
    int start = t * CH;
    int end = start + CH; if (end > NN) end = NN;
    int s = 0;
    for (int i = start; i < end; i++) s += d_cnt_in[i];
    sums[t] = s;
    __syncthreads();
    for (int off = 1; off < 1024; off <<= 1) {
        int v = (t >= off) ? sums[t - off] : 0;
        __syncthreads();
        sums[t] += v;
        __syncthreads();
    }
    int excl = (t == 0) ? 0 : sums[t - 1];
    for (int i = start; i < end; i++) {
        d_ptr[i] = excl;
        excl += d_cnt_in[i];
    }
    if (t == 1023) d_ptr[NN] = excl;
}

// dinv + write self-loop CSR entry at row head, init fill cursor past it
__global__ void k_dinvself() {
    int n = blockIdx.x * blockDim.x + threadIdx.x;
    if (n >= NN) return;
    float di = rsqrtf((float)d_cnt_in[n]);   // cnt includes self
    d_dinv[n] = di;
    int p = d_ptr[n];
    d_csr[p] = make_int2(n, __float_as_int(di * di));
    d_pos[n] = p + 1;
}

__global__ void k_fill(const int* __restrict__ ei, int E_) {
    int e = blockIdx.x * blockDim.x + threadIdx.x;
    if (e >= E_) return;
    int r = ei[e], c = ei[E_ + e];
    float nm = d_dinv[r] * d_dinv[c];
    int p = atomicAdd(&d_pos[c], 1);
    d_csr[p] = make_int2(r, __float_as_int(nm));
}

// ---------------- layer 1: scalar gather + fused stats ----------------------
__global__ void k_gather1(const float* __restrict__ x) {
    int n = blockIdx.x * blockDim.x + threadIdx.x;
    float s = 0.f;
    if (n < NN) {
        int p = d_ptr[n], en = d_ptr[n + 1];
        for (; p + 3 < en; p += 4) {
            int2 v0 = __ldg(&d_csr[p]);
            int2 v1 = __ldg(&d_csr[p + 1]);
            int2 v2 = __ldg(&d_csr[p + 2]);
            int2 v3 = __ldg(&d_csr[p + 3]);
            float x0 = __ldg(&x[v0.x]), x1 = __ldg(&x[v1.x]);
            float x2 = __ldg(&x[v2.x]), x3 = __ldg(&x[v3.x]);
            s = fmaf(x0, __int_as_float(v0.y), s);
            s = fmaf(x1, __int_as_float(v1.y), s);
            s = fmaf(x2, __int_as_float(v2.y), s);
            s = fmaf(x3, __int_as_float(v3.y), s);
        }
        for (; p < en; p++) {
            int2 v = __ldg(&d_csr[p]);
            s = fmaf(__ldg(&x[v.x]), __int_as_float(v.y), s);
        }
        d_s[n] = s;
    }
    float q = s * s;
    for (int o = 16; o; o >>= 1) {
        s += __shfl_down_sync(0xffffffffu, s, o);
        q += __shfl_down_sync(0xffffffffu, q, o);
    }
    __shared__ float sh[2][8];
    int w = threadIdx.x >> 5;
    if ((threadIdx.x & 31) == 0) { sh[0][w] = s; sh[1][w] = q; }
    __syncthreads();
    if (threadIdx.x == 0) {
        s = 0.f; q = 0.f;
        for (int i = 0; i < 8; i++) { s += sh[0][i]; q += sh[1][i]; }
        atomicAdd(&d_ssum[0], s);
        atomicAdd(&d_ssum[1], q);
    }
}

// ---------------- GEMM: d_h = relu(affine(src)) @ W -------------------------
// Affine (BN+ReLU params) computed inline from raw stats.
// FROM_S: src = d_s scalar, affine folds W1; else src = d_y, L indexes stats.
template <bool FROM_S>
__global__ void k_gemm(int L, const float* __restrict__ W,
                       const float* __restrict__ Wp,   // W1 (FROM_S only)
                       const float* __restrict__ g, const float* __restrict__ bt) {
    __shared__ float Zs[FF][FF + 1];   // [k][localrow]
    __shared__ float Ws[FF][FF];       // [k][col]
    __shared__ float sa[FF], sc[FF];
    int t = threadIdx.x;
    int base = blockIdx.x * FF;

    if (t < FF) {
        float inv_n = 1.0f / (float)NN;
        if (FROM_S) {
            float ms = d_ssum[0] * inv_n;
            float vs = d_ssum[1] * inv_n - ms * ms;
            float w1 = Wp[t];
            float ia = g[t] * rsqrtf(vs * w1 * w1 + BN_EPS);
            float A = ia * w1;
            sa[t] = A;
            sc[t] = bt[t] - A * ms;
        } else {
            float m = d_fsum[L][t] * inv_n;
            float v = d_fsq[L][t] * inv_n - m * m;
            float ia = g[t] * rsqrtf(v + BN_EPS);
            sa[t] = ia;
            sc[t] = bt[t] - ia * m;
        }
    }
    {
        const float4* W4 = (const float4*)W;
        float4* Ws4 = (float4*)&Ws[0][0];
        #pragma unroll
        for (int i = 0; i < 4; i++) Ws4[t + i * 256] = W4[t + i * 256];
    }
    __syncthreads();

    int lr = t >> 2;
    int cg = (t & 3) * 4;
    int row = base + lr;
    if (FROM_S) {
        float sval = (row < NN) ? d_s[row] : 0.f;
        #pragma unroll
        for (int i = 0; i < 4; i++) {
            int cc = cg + i * 16;
            #pragma unroll
            for (int j = 0; j < 4; j++)
                Zs[cc + j][lr] = fmaxf(sa[cc + j] * sval + sc[cc + j], 0.f);
        }
    } else {
        #pragma unroll
        for (int i = 0; i < 4; i++) {
            int cc = cg + i * 16;
            float4 v = (row < NN) ? *(const float4*)(d_y + (size_t)row * FF + cc)
                                  : make_float4(0.f, 0.f, 0.f, 0.f);
            Zs[cc + 0][lr] = fmaxf(sa[cc + 0] * v.x + sc[cc + 0], 0.f);
            Zs[cc + 1][lr] = fmaxf(sa[cc + 1] * v.y + sc[cc + 1], 0.f);
            Zs[cc + 2][lr] = fmaxf(sa[cc + 2] * v.z + sc[cc + 2], 0.f);
            Zs[cc + 3][lr] = fmaxf(sa[cc + 3] * v.w + sc[cc + 3], 0.f);
        }
    }
    __syncthreads();

    int tx = t & 15, ty = t >> 4;
    float acc[4][4] = {};
    #pragma unroll 16
    for (int k = 0; k < FF; k++) {
        float zr[4], wc[4];
        #pragma unroll
        for (int r = 0; r < 4; r++) zr[r] = Zs[k][ty + 16 * r];
        #pragma unroll
        for (int j = 0; j < 4; j++) wc[j] = Ws[k][tx + 16 * j];
        #pragma unroll
        for (int r = 0; r < 4; r++)
            #pragma unroll
            for (int j = 0; j < 4; j++)
                acc[r][j] = fmaf(zr[r], wc[j], acc[r][j]);
    }
    #pragma unroll
    for (int r = 0; r < 4; r++) {
        int orow = base + ty + 16 * r;
        if (orow < NN) {
            #pragma unroll
            for (int j = 0; j < 4; j++)
                d_h[(size_t)orow * FF + tx + 16 * j] = acc[r][j];
        }
    }
}

// ---------------- 64-wide gather: 16 threads/node, fused stats ---------------
// Lane layout: fl = lane&15 owns float4 of features [4fl,4fl+3]; sub = lane>>4
// selects one of 2 concurrent nodes per warp (2 independent load chains).
// 4-deep edge unroll -> up to 16 x 128B lines in flight per warp.
__global__ void k_gather64(int L) {
    __shared__ float4 smS[8][32];
    __shared__ float4 smQ[8][32];
    int t = threadIdx.x;
    int lane = t & 31, w = t >> 5;          // 8 warps / block
    int fl = lane & 15, sub = lane >> 4;
    float4 rS = make_float4(0.f, 0.f, 0.f, 0.f);
    float4 rQ = make_float4(0.f, 0.f, 0.f, 0.f);
    const float4* hb = (const float4*)d_h;

    for (int n = (blockIdx.x * 8 + w) * 2 + sub; n < NN; n += gridDim.x * 16) {
        int p = d_ptr[n], en = d_ptr[n + 1];
        float4 acc = make_float4(0.f, 0.f, 0.f, 0.f);
        for (; p + 3 < en; p += 4) {
            int2 v0 = __ldg(&d_csr[p]);
            int2 v1 = __ldg(&d_csr[p + 1]);
            int2 v2 = __ldg(&d_csr[p + 2]);
            int2 v3 = __ldg(&d_csr[p + 3]);
            float4 h0 = __ldg(hb + (size_t)v0.x * 16 + fl);
            float4 h1 = __ldg(hb + (size_t)v1.x * 16 + fl);
            float4 h2 = __ldg(hb + (size_t)v2.x * 16 + fl);
            float4 h3 = __ldg(hb + (size_t)v3.x * 16 + fl);
            float m0 = __int_as_float(v0.y), m1 = __int_as_float(v1.y);
            float m2 = __int_as_float(v2.y), m3 = __int_as_float(v3.y);
            acc.x = fmaf(h0.x, m0, acc.x); acc.y = fmaf(h0.y, m0, acc.y);
            acc.z = fmaf(h0.z, m0, acc.z); acc.w = fmaf(h0.w, m0, acc.w);
            acc.x = fmaf(h1.x, m1, acc.x); acc.y = fmaf(h1.y, m1, acc.y);
            acc.z = fmaf(h1.z, m1, acc.z); acc.w = fmaf(h1.w, m1, acc.w);
            acc.x = fmaf(h2.x, m2, acc.x); acc.y = fmaf(h2.y, m2, acc.y);
            acc.z = fmaf(h2.z, m2, acc.z); acc.w = fmaf(h2.w, m2, acc.w);
            acc.x = fmaf(h3.x, m3, acc.x); acc.y = fmaf(h3.y, m3, acc.y);
            acc.z = fmaf(h3.z, m3, acc.z); acc.w = fmaf(h3.w, m3, acc.w);
        }
        for (; p < en; p++) {
            int2 v = __ldg(&d_csr[p]);
            float4 h0 = __ldg(hb + (size_t)v.x * 16 + fl);
            float m0 = __int_as_float(v.y);
            acc.x = fmaf(h0.x, m0, acc.x); acc.y = fmaf(h0.y, m0, acc.y);
            acc.z = fmaf(h0.z, m0, acc.z); acc.w = fmaf(h0.w, m0, acc.w);
        }
        ((float4*)(d_y + (size_t)n * FF))[fl] = acc;
        rS.x += acc.x; rS.y += acc.y; rS.z += acc.z; rS.w += acc.w;
        rQ.x = fmaf(acc.x, acc.x, rQ.x); rQ.y = fmaf(acc.y, acc.y, rQ.y);
        rQ.z = fmaf(acc.z, acc.z, rQ.z); rQ.w = fmaf(acc.w, acc.w, rQ.w);
    }
    smS[w][lane] = rS; smQ[w][lane] = rQ;
    __syncthreads();
    if (t < 32) {
        float4 s = make_float4(0.f, 0.f, 0.f, 0.f);
        float4 q = make_float4(0.f, 0.f, 0.f, 0.f);
        #pragma unroll
        for (int i = 0; i < 8; i++) {
            float4 a = smS[i][t], b = smQ[i][t];
            s.x += a.x; s.y += a.y; s.z += a.z; s.w += a.w;
            q.x += b.x; q.y += b.y; q.z += b.z; q.w += b.w;
        }
        // fold sub-halves (lane and lane+16 hold same features)
        s.x += __shfl_down_sync(0xffffffffu, s.x, 16);
        s.y += __shfl_down_sync(0xffffffffu, s.y, 16);
        s.z += __shfl_down_sync(0xffffffffu, s.z, 16);
        s.w += __shfl_down_sync(0xffffffffu, s.w, 16);
        q.x += __shfl_down_sync(0xffffffffu, q.x, 16);
        q.y += __shfl_down_sync(0xffffffffu, q.y, 16);
        q.z += __shfl_down_sync(0xffffffffu, q.z, 16);
        q.w += __shfl_down_sync(0xffffffffu, q.w, 16);
        if (t < 16) {
            atomicAdd(&d_fsum[L][4 * t + 0], s.x);
            atomicAdd(&d_fsum[L][4 * t + 1], s.y);
            atomicAdd(&d_fsum[L][4 * t + 2], s.z);
            atomicAdd(&d_fsum[L][4 * t + 3], s.w);
            atomicAdd(&d_fsq[L][4 * t + 0], q.x);
            atomicAdd(&d_fsq[L][4 * t + 1], q.y);
            atomicAdd(&d_fsq[L][4 * t + 2], q.z);
            atomicAdd(&d_fsq[L][4 * t + 3], q.w);
        }
    }
}

// ---------------- pooling (affine4 inline) + head ----------------------------
__global__ void k_pool(const int* __restrict__ batch,
                       const float* __restrict__ g4, const float* __restrict__ bt4) {
    int t = threadIdx.x;
    int f = t & 63, rg = t >> 6;
    int base = blockIdx.x * 256;
    float inv_n = 1.0f / (float)NN;
    float m = d_fsum[2][f] * inv_n;
    float v = d_fsq[2][f] * inv_n - m * m;
    float ia = g4[f] * rsqrtf(v + BN_EPS);
    float af = ia, cf = bt4[f] - ia * m;
    float acc = 0.f, cacc = 0.f;
    int gcur = -1;
    for (int i = 0; i < 64; i++) {
        int n = base + rg + 4 * i;
        if (n >= NN) break;
        int g = batch[n];
        if (g != gcur) {
            if (gcur >= 0) {
                atomicAdd(&d_pooled[gcur * FF + f], acc);
                if (f == 0) atomicAdd(&d_cnt[gcur], cacc);
            }
            gcur = g; acc = 0.f; cacc = 0.f;
        }
        float vv = fmaxf(af * d_y[(size_t)n * FF + f] + cf, 0.f);
        acc += vv; cacc += 1.f;
    }
    if (gcur >= 0) {
        atomicAdd(&d_pooled[gcur * FF + f], acc);
        if (f == 0) atomicAdd(&d_cnt[gcur], cacc);
    }
}

__global__ void k_fc(const float* __restrict__ fw1, const float* __restrict__ fb1,
                     const float* __restrict__ fw2, const float* __restrict__ fb2,
                     float* __restrict__ out) {
    __shared__ float P[GG][FF];
    __shared__ float H[GG][128];
    int t = threadIdx.x;   // 128 threads
    for (int i = t; i < GG * FF; i += 128) {
        int g = i >> 6;
        float cc = d_cnt[g]; cc = (cc < 1.f) ? 1.f : cc;
        P[g][i & 63] = d_pooled[i] / cc;
    }
    __syncthreads();
    int j = t;
    for (int g = 0; g < GG; g++) {
        float s = fb1[j];
        #pragma unroll 8
        for (int f = 0; f < FF; f++) s = fmaf(P[g][f], fw1[j * FF + f], s);
        H[g][j] = fmaxf(s, 0.f);
    }
    __syncthreads();
    for (int i = t; i < GG * 10; i += 128) {
        int g = i / 10, k = i % 10;
        float s = fb2[k];
        #pragma unroll 8
        for (int jj = 0; jj < 128; jj++) s = fmaf(H[g][jj], fw2[k * 128 + jj], s);
        out[i] = s;
    }
}

// ---------------- launch -----------------------------------------------------
extern "C" void kernel_launch(void* const* d_in, const int* in_sizes, int n_in,
                              void* d_out, int out_size) {
    const float* x   = (const float*)d_in[0];
    const int*   ei  = (const int*)d_in[1];
    const int*   bat = (const int*)d_in[2];
    const float* W1  = (const float*)d_in[3];
    const float* g1  = (const float*)d_in[5];
    const float* bt1 = (const float*)d_in[6];
    const float* W2  = (const float*)d_in[7];
    const float* g2  = (const float*)d_in[9];
    const float* bt2 = (const float*)d_in[10];
    const float* W3  = (const float*)d_in[11];
    const float* g3  = (const float*)d_in[13];
    const float* bt3 = (const float*)d_in[14];
    const float* W4  = (const float*)d_in[15];
    const float* g4  = (const float*)d_in[17];
    const float* bt4 = (const float*)d_in[18];
    const float* fw1 = (const float*)d_in[19];
    const float* fb1 = (const float*)d_in[20];
    const float* fw2 = (const float*)d_in[21];
    const float* fb2 = (const float*)d_in[22];
    float* out = (float*)d_out;

    int E_ = in_sizes[1] / 2;
    if (E_ > EE) E_ = EE;

    const int TB = 256;
    int nb_n = (NN + TB - 1) / TB;
    int nb_e = (E_ + TB - 1) / TB;
    int nb_g = (NN + 63) / 64;
    const int GATHER_BLKS = 592;      // 4 blocks/SM target

    // CSR build (self-loops embedded)
    k_zero<<<nb_n, TB>>>();
    k_count<<<nb_e, TB>>>(ei, E_);
    k_scan<<<1, 1024>>>();
    k_dinvself<<<nb_n, TB>>>();
    k_fill<<<nb_e, TB>>>(ei, E_);

    // layer 1 (scalar)
    k_gather1<<<nb_n, TB>>>(x);

    // layer 2
    k_gemm<true><<<nb_g, TB>>>(0, W2, W1, g1, bt1);
    k_gather64<<<GATHER_BLKS, TB>>>(0);

    // layer 3
    k_gemm<false><<<nb_g, TB>>>(0, W3, nullptr, g2, bt2);
    k_gather64<<<GATHER_BLKS, TB>>>(1);

    // layer 4
    k_gemm<false><<<nb_g, TB>>>(1, W4, nullptr, g3, bt3);
    k_gather64<<<GATHER_BLKS, TB>>>(2);

    // pool + head
    k_pool<<<(NN + 255) / 256, TB>>>(bat, g4, bt4);
    k_fc<<<1, 128>>>(fw1, fb1, fw2, fb2, out);
}

// round 6
// speedup vs baseline: 2.0281x; 1.7894x over previous
#include <cuda_runtime.h>
#include <cstdint>

#define NN 50000
#define EE 800000
#define GG 64
#define FF 64
#define BN_EPS 1e-5f

// ---------------- scratch (static device globals; zero-initialized at load) --
// Invariant: d_cnt_in, d_ssum, d_fsum, d_fsq, d_pooled, d_cnt are ZERO at entry
// of every kernel_launch call (static init covers call 1; k_fc tail re-zeros).
__device__ float d_h[(size_t)NN * FF];     // GEMM output / gather source
__device__ float d_y[(size_t)NN * FF];     // gather output / GEMM input
__device__ float d_s[NN];                  // layer-1 scalar aggregate
__device__ float d_dinv[NN];
__device__ int   d_cnt_in[NN];             // in-degree counters (zeroed in tail)
__device__ int   d_ptr[NN + 1];            // CSR row pointers (by dst)
__device__ int   d_pos[NN];                // fill cursors
__device__ int2  d_csr[EE + NN];           // {src, bitcast(norm)}; self incl.
__device__ float d_ssum[2];                // scalar sum / sumsq (layer 1)
__device__ float d_fsum[3][FF];            // per-feature sums, layers 2..4
__device__ float d_fsq[3][FF];
__device__ float d_pooled[GG * FF];
__device__ float d_cnt[GG];

// ---------------- setup ------------------------------------------------------
// counters arrive zeroed; self-loop handled as +1 in scan.
__global__ void k_count(const int* __restrict__ ei, int E_) {
    int e = blockIdx.x * blockDim.x + threadIdx.x;
    if (e < E_) atomicAdd(&d_cnt_in[ei[E_ + e]], 1);
}

// single-block: exclusive scan of (cnt_in+1) -> d_ptr, then per-row dinv,
// self-loop CSR entry, fill cursor. No extra sync needed for the tail: each
// thread only uses its own running prefix.
__global__ void k_scan_dinvself() {
    __shared__ int sums[1024];
    int t = threadIdx.x;
    const int CH = (NN + 1023) / 1024;   // 49
    int start = t * CH;
    int end = start + CH; if (end > NN) end = NN;
    int s = 0;
    for (int i = start; i < end; i++) s += d_cnt_in[i] + 1;   // +1 self-loop
    sums[t] = s;
    __syncthreads();
    for (int off = 1; off < 1024; off <<= 1) {
        int v = (t >= off) ? sums[t - off] : 0;
        __syncthreads();
        sums[t] += v;
        __syncthreads();
    }
    int excl = (t == 0) ? 0 : sums[t - 1];
    for (int i = start; i < end; i++) {
        int deg = d_cnt_in[i] + 1;
        d_ptr[i] = excl;
        float di = rsqrtf((float)deg);
        d_dinv[i] = di;
        d_csr[excl] = make_int2(i, __float_as_int(di * di));  // self entry
        d_pos[i] = excl + 1;
        excl += deg;
    }
    if (t == 1023) d_ptr[NN] = excl;
}

__global__ void k_fill(const int* __restrict__ ei, int E_) {
    int e = blockIdx.x * blockDim.x + threadIdx.x;
    if (e >= E_) return;
    int r = ei[e], c = ei[E_ + e];
    float nm = d_dinv[r] * d_dinv[c];
    int p = atomicAdd(&d_pos[c], 1);
    d_csr[p] = make_int2(r, __float_as_int(nm));
}

// ---------------- layer 1: scalar gather + fused stats ----------------------
__global__ void k_gather1(const float* __restrict__ x) {
    int n = blockIdx.x * blockDim.x + threadIdx.x;
    float s = 0.f;
    if (n < NN) {
        int p = d_ptr[n], en = d_ptr[n + 1];
        for (; p + 3 < en; p += 4) {
            int2 v0 = __ldg(&d_csr[p]);
            int2 v1 = __ldg(&d_csr[p + 1]);
            int2 v2 = __ldg(&d_csr[p + 2]);
            int2 v3 = __ldg(&d_csr[p + 3]);
            float x0 = __ldg(&x[v0.x]), x1 = __ldg(&x[v1.x]);
            float x2 = __ldg(&x[v2.x]), x3 = __ldg(&x[v3.x]);
            s = fmaf(x0, __int_as_float(v0.y), s);
            s = fmaf(x1, __int_as_float(v1.y), s);
            s = fmaf(x2, __int_as_float(v2.y), s);
            s = fmaf(x3, __int_as_float(v3.y), s);
        }
        for (; p < en; p++) {
            int2 v = __ldg(&d_csr[p]);
            s = fmaf(__ldg(&x[v.x]), __int_as_float(v.y), s);
        }
        d_s[n] = s;
    }
    float q = s * s;
    for (int o = 16; o; o >>= 1) {
        s += __shfl_down_sync(0xffffffffu, s, o);
        q += __shfl_down_sync(0xffffffffu, q, o);
    }
    __shared__ float sh[2][8];
    int w = threadIdx.x >> 5;
    if ((threadIdx.x & 31) == 0) { sh[0][w] = s; sh[1][w] = q; }
    __syncthreads();
    if (threadIdx.x == 0) {
        s = 0.f; q = 0.f;
        for (int i = 0; i < 8; i++) { s += sh[0][i]; q += sh[1][i]; }
        atomicAdd(&d_ssum[0], s);
        atomicAdd(&d_ssum[1], q);
    }
}

// ---------------- GEMM: d_h = relu(affine(src)) @ W -------------------------
template <bool FROM_S>
__global__ void k_gemm(int L, const float* __restrict__ W,
                       const float* __restrict__ Wp,   // W1 (FROM_S only)
                       const float* __restrict__ g, const float* __restrict__ bt) {
    __shared__ float Zs[FF][FF + 1];   // [k][localrow]
    __shared__ float Ws[FF][FF];       // [k][col]
    __shared__ float sa[FF], sc[FF];
    int t = threadIdx.x;
    int base = blockIdx.x * FF;

    if (t < FF) {
        float inv_n = 1.0f / (float)NN;
        if (FROM_S) {
            float ms = d_ssum[0] * inv_n;
            float vs = d_ssum[1] * inv_n - ms * ms;
            float w1 = Wp[t];
            float ia = g[t] * rsqrtf(vs * w1 * w1 + BN_EPS);
            float A = ia * w1;
            sa[t] = A;
            sc[t] = bt[t] - A * ms;
        } else {
            float m = d_fsum[L][t] * inv_n;
            float v = d_fsq[L][t] * inv_n - m * m;
            float ia = g[t] * rsqrtf(v + BN_EPS);
            sa[t] = ia;
            sc[t] = bt[t] - ia * m;
        }
    }
    {
        const float4* W4 = (const float4*)W;
        float4* Ws4 = (float4*)&Ws[0][0];
        #pragma unroll
        for (int i = 0; i < 4; i++) Ws4[t + i * 256] = W4[t + i * 256];
    }
    __syncthreads();

    int lr = t >> 2;
    int cg = (t & 3) * 4;
    int row = base + lr;
    if (FROM_S) {
        float sval = (row < NN) ? d_s[row] : 0.f;
        #pragma unroll
        for (int i = 0; i < 4; i++) {
            int cc = cg + i * 16;
            #pragma unroll
            for (int j = 0; j < 4; j++)
                Zs[cc + j][lr] = fmaxf(sa[cc + j] * sval + sc[cc + j], 0.f);
        }
    } else {
        #pragma unroll
        for (int i = 0; i < 4; i++) {
            int cc = cg + i * 16;
            float4 v = (row < NN) ? *(const float4*)(d_y + (size_t)row * FF + cc)
                                  : make_float4(0.f, 0.f, 0.f, 0.f);
            Zs[cc + 0][lr] = fmaxf(sa[cc + 0] * v.x + sc[cc + 0], 0.f);
            Zs[cc + 1][lr] = fmaxf(sa[cc + 1] * v.y + sc[cc + 1], 0.f);
            Zs[cc + 2][lr] = fmaxf(sa[cc + 2] * v.z + sc[cc + 2], 0.f);
            Zs[cc + 3][lr] = fmaxf(sa[cc + 3] * v.w + sc[cc + 3], 0.f);
        }
    }
    __syncthreads();

    int tx = t & 15, ty = t >> 4;
    float acc[4][4] = {};
    #pragma unroll 16
    for (int k = 0; k < FF; k++) {
        float zr[4], wc[4];
        #pragma unroll
        for (int r = 0; r < 4; r++) zr[r] = Zs[k][ty + 16 * r];
        #pragma unroll
        for (int j = 0; j < 4; j++) wc[j] = Ws[k][tx + 16 * j];
        #pragma unroll
        for (int r = 0; r < 4; r++)
            #pragma unroll
            for (int j = 0; j < 4; j++)
                acc[r][j] = fmaf(zr[r], wc[j], acc[r][j]);
    }
    #pragma unroll
    for (int r = 0; r < 4; r++) {
        int orow = base + ty + 16 * r;
        if (orow < NN) {
            #pragma unroll
            for (int j = 0; j < 4; j++)
                d_h[(size_t)orow * FF + tx + 16 * j] = acc[r][j];
        }
    }
}

// ---------------- 64-wide gather: 16 threads/node, fused stats ---------------
__global__ void k_gather64(int L) {
    __shared__ float4 smS[8][32];
    __shared__ float4 smQ[8][32];
    int t = threadIdx.x;
    int lane = t & 31, w = t >> 5;          // 8 warps / block
    int fl = lane & 15, sub = lane >> 4;
    float4 rS = make_float4(0.f, 0.f, 0.f, 0.f);
    float4 rQ = make_float4(0.f, 0.f, 0.f, 0.f);
    const float4* hb = (const float4*)d_h;

    for (int n = (blockIdx.x * 8 + w) * 2 + sub; n < NN; n += gridDim.x * 16) {
        int p = d_ptr[n], en = d_ptr[n + 1];
        float4 acc = make_float4(0.f, 0.f, 0.f, 0.f);
        for (; p + 3 < en; p += 4) {
            int2 v0 = __ldg(&d_csr[p]);
            int2 v1 = __ldg(&d_csr[p + 1]);
            int2 v2 = __ldg(&d_csr[p + 2]);
            int2 v3 = __ldg(&d_csr[p + 3]);
            float4 h0 = __ldg(hb + (size_t)v0.x * 16 + fl);
            float4 h1 = __ldg(hb + (size_t)v1.x * 16 + fl);
            float4 h2 = __ldg(hb + (size_t)v2.x * 16 + fl);
            float4 h3 = __ldg(hb + (size_t)v3.x * 16 + fl);
            float m0 = __int_as_float(v0.y), m1 = __int_as_float(v1.y);
            float m2 = __int_as_float(v2.y), m3 = __int_as_float(v3.y);
            acc.x = fmaf(h0.x, m0, acc.x); acc.y = fmaf(h0.y, m0, acc.y);
            acc.z = fmaf(h0.z, m0, acc.z); acc.w = fmaf(h0.w, m0, acc.w);
            acc.x = fmaf(h1.x, m1, acc.x); acc.y = fmaf(h1.y, m1, acc.y);
            acc.z = fmaf(h1.z, m1, acc.z); acc.w = fmaf(h1.w, m1, acc.w);
            acc.x = fmaf(h2.x, m2, acc.x); acc.y = fmaf(h2.y, m2, acc.y);
            acc.z = fmaf(h2.z, m2, acc.z); acc.w = fmaf(h2.w, m2, acc.w);
            acc.x = fmaf(h3.x, m3, acc.x); acc.y = fmaf(h3.y, m3, acc.y);
            acc.z = fmaf(h3.z, m3, acc.z); acc.w = fmaf(h3.w, m3, acc.w);
        }
        for (; p < en; p++) {
            int2 v = __ldg(&d_csr[p]);
            float4 h0 = __ldg(hb + (size_t)v.x * 16 + fl);
            float m0 = __int_as_float(v.y);
            acc.x = fmaf(h0.x, m0, acc.x); acc.y = fmaf(h0.y, m0, acc.y);
            acc.z = fmaf(h0.z, m0, acc.z); acc.w = fmaf(h0.w, m0, acc.w);
        }
        ((float4*)(d_y + (size_t)n * FF))[fl] = acc;
        rS.x += acc.x; rS.y += acc.y; rS.z += acc.z; rS.w += acc.w;
        rQ.x = fmaf(acc.x, acc.x, rQ.x); rQ.y = fmaf(acc.y, acc.y, rQ.y);
        rQ.z = fmaf(acc.z, acc.z, rQ.z); rQ.w = fmaf(acc.w, acc.w, rQ.w);
    }
    smS[w][lane] = rS; smQ[w][lane] = rQ;
    __syncthreads();
    if (t < 32) {
        float4 s = make_float4(0.f, 0.f, 0.f, 0.f);
        float4 q = make_float4(0.f, 0.f, 0.f, 0.f);
        #pragma unroll
        for (int i = 0; i < 8; i++) {
            float4 a = smS[i][t], b = smQ[i][t];
            s.x += a.x; s.y += a.y; s.z += a.z; s.w += a.w;
            q.x += b.x; q.y += b.y; q.z += b.z; q.w += b.w;
        }
        s.x += __shfl_down_sync(0xffffffffu, s.x, 16);
        s.y += __shfl_down_sync(0xffffffffu, s.y, 16);
        s.z += __shfl_down_sync(0xffffffffu, s.z, 16);
        s.w += __shfl_down_sync(0xffffffffu, s.w, 16);
        q.x += __shfl_down_sync(0xffffffffu, q.x, 16);
        q.y += __shfl_down_sync(0xffffffffu, q.y, 16);
        q.z += __shfl_down_sync(0xffffffffu, q.z, 16);
        q.w += __shfl_down_sync(0xffffffffu, q.w, 16);
        if (t < 16) {
            atomicAdd(&d_fsum[L][4 * t + 0], s.x);
            atomicAdd(&d_fsum[L][4 * t + 1], s.y);
            atomicAdd(&d_fsum[L][4 * t + 2], s.z);
            atomicAdd(&d_fsum[L][4 * t + 3], s.w);
            atomicAdd(&d_fsq[L][4 * t + 0], q.x);
            atomicAdd(&d_fsq[L][4 * t + 1], q.y);
            atomicAdd(&d_fsq[L][4 * t + 2], q.z);
            atomicAdd(&d_fsq[L][4 * t + 3], q.w);
        }
    }
}

// ---------------- pooling (BN4+ReLU inline) ----------------------------------
__global__ void k_pool(const int* __restrict__ batch,
                       const float* __restrict__ g4, const float* __restrict__ bt4) {
    int t = threadIdx.x;
    int f = t & 63, rg = t >> 6;
    int base = blockIdx.x * 256;
    float inv_n = 1.0f / (float)NN;
    float m = d_fsum[2][f] * inv_n;
    float v = d_fsq[2][f] * inv_n - m * m;
    float ia = g4[f] * rsqrtf(v + BN_EPS);
    float af = ia, cf = bt4[f] - ia * m;
    float acc = 0.f, cacc = 0.f;
    int gcur = -1;
    for (int i = 0; i < 64; i++) {
        int n = base + rg + 4 * i;
        if (n >= NN) break;
        int g = batch[n];
        if (g != gcur) {
            if (gcur >= 0) {
                atomicAdd(&d_pooled[gcur * FF + f], acc);
                if (f == 0) atomicAdd(&d_cnt[gcur], cacc);
            }
            gcur = g; acc = 0.f; cacc = 0.f;
        }
        float vv = fmaxf(af * d_y[(size_t)n * FF + f] + cf, 0.f);
        acc += vv; cacc += 1.f;
    }
    if (gcur >= 0) {
        atomicAdd(&d_pooled[gcur * FF + f], acc);
        if (f == 0) atomicAdd(&d_cnt[gcur], cacc);
    }
}

// ---------------- MLP head: one block per graph, transposed fw1 in smem ------
// Also re-zeros all accumulators for the next call (tail-zero invariant).
__global__ void k_fc(const float* __restrict__ fw1, const float* __restrict__ fb1,
                     const float* __restrict__ fw2, const float* __restrict__ fb2,
                     float* __restrict__ out) {
    __shared__ float FWt[FF][129];     // FWt[f][j] = fw1[j*64+f], pad stride 129
    __shared__ float P[FF];
    __shared__ float H[128];
    int t = threadIdx.x;               // 128 threads
    int g = blockIdx.x;                // 64 blocks

    // stage fw1 transposed: coalesced global read, conflict-free smem write
    for (int idx = t; idx < 128 * FF; idx += 128) {
        int j = idx >> 6, f = idx & 63;
        FWt[f][j] = fw1[idx];
    }
    if (t < FF) {
        float cc = d_cnt[g]; cc = (cc < 1.f) ? 1.f : cc;
        P[t] = d_pooled[g * FF + t] / cc;
    }
    __syncthreads();

    // layer 1: H[j] = relu(fb1[j] + sum_f P[f]*FWt[f][j]) — lanes j contiguous
    {
        float s = fb1[t];
        #pragma unroll 16
        for (int f = 0; f < FF; f++) s = fmaf(P[f], FWt[f][t], s);
        H[t] = fmaxf(s, 0.f);
    }
    __syncthreads();

    // layer 2: 10 outputs; threads 0..9
    if (t < 10) {
        float s = fb2[t];
        #pragma unroll 16
        for (int j = 0; j < 128; j++) s = fmaf(H[j], fw2[t * 128 + j], s);
        out[g * 10 + t] = s;
    }

    // ---- tail-zero for next call (all readers of these arrays have finished)
    if (t < FF) d_pooled[g * FF + t] = 0.f;
    if (t == 0) d_cnt[g] = 0.f;
    for (int i = g * 128 + t; i < NN; i += GG * 128) d_cnt_in[i] = 0;
    if (g == 0) {
        if (t < 2) d_ssum[t] = 0.f;
        if (t < 128) {
            ((float*)d_fsum)[t] = 0.f; ((float*)d_fsum)[t + 64] = 0.f;
            ((float*)d_fsq)[t]  = 0.f; ((float*)d_fsq)[t + 64]  = 0.f;
        }
        if (t < 64) { ((float*)d_fsum)[128 + t] = 0.f; ((float*)d_fsq)[128 + t] = 0.f; }
    }
}

// ---------------- launch -----------------------------------------------------
extern "C" void kernel_launch(void* const* d_in, const int* in_sizes, int n_in,
                              void* d_out, int out_size) {
    const float* x   = (const float*)d_in[0];
    const int*   ei  = (const int*)d_in[1];
    const int*   bat = (const int*)d_in[2];
    const float* W1  = (const float*)d_in[3];
    const float* g1  = (const float*)d_in[5];
    const float* bt1 = (const float*)d_in[6];
    const float* W2  = (const float*)d_in[7];
    const float* g2  = (const float*)d_in[9];
    const float* bt2 = (const float*)d_in[10];
    const float* W3  = (const float*)d_in[11];
    const float* g3  = (const float*)d_in[13];
    const float* bt3 = (const float*)d_in[14];
    const float* W4  = (const float*)d_in[15];
    const float* g4  = (const float*)d_in[17];
    const float* bt4 = (const float*)d_in[18];
    const float* fw1 = (const float*)d_in[19];
    const float* fb1 = (const float*)d_in[20];
    const float* fw2 = (const float*)d_in[21];
    const float* fb2 = (const float*)d_in[22];
    float* out = (float*)d_out;

    int E_ = in_sizes[1] / 2;
    if (E_ > EE) E_ = EE;

    const int TB = 256;
    int nb_n = (NN + TB - 1) / TB;
    int nb_e = (E_ + TB - 1) / TB;
    int nb_g = (NN + 63) / 64;
    const int GATHER_BLKS = 592;

    // CSR build (self-loops embedded); counters pre-zeroed by tail invariant
    k_count<<<nb_e, TB>>>(ei, E_);            // launch 0
    k_scan_dinvself<<<1, 1024>>>();           // launch 1
    k_fill<<<nb_e, TB>>>(ei, E_);             // launch 2

    // layer 1 (scalar)  — launch index 3: ncu capture target
    k_gather1<<<nb_n, TB>>>(x);

    // layer 2
    k_gemm<true><<<nb_g, TB>>>(0, W2, W1, g1, bt1);
    k_gather64<<<GATHER_BLKS, TB>>>(0);

    // layer 3
    k_gemm<false><<<nb_g, TB>>>(0, W3, nullptr, g2, bt2);
    k_gather64<<<GATHER_BLKS, TB>>>(1);

    // layer 4
    k_gemm<false><<<nb_g, TB>>>(1, W4, nullptr, g3, bt3);
    k_gather64<<<GATHER_BLKS, TB>>>(2);

    // pool + head (+ tail-zero)
    k_pool<<<(NN + 255) / 256, TB>>>(bat, g4, bt4);
    k_fc<<<GG, 128>>>(fw1, fb1, fw2, fb2, out);
}

// round 7
// speedup vs baseline: 2.6089x; 1.2864x over previous
#include <cuda_runtime.h>
#include <cuda_fp16.h>
#include <cstdint>

#define NN 50000
#define EE 800000
#define GG 64
#define FF 64
#define BN_EPS 1e-5f

// ---------------- scratch (static device globals; zero-initialized at load) --
// Invariant: d_cnt_in, d_ssum, d_fsum, d_fsq, d_pooled, d_cnt are ZERO at entry
// of every kernel_launch call (static init covers call 1; k_fc tail re-zeros).
__device__ __half d_h[(size_t)NN * FF];    // GEMM output (fp16) / gather source
__device__ float  d_y[(size_t)NN * FF];    // gather output / GEMM input (fp32)
__device__ float  d_s[NN];                 // layer-1 scalar aggregate
__device__ float  d_dinv[NN];
__device__ int    d_cnt_in[NN];            // in-degree counters (zeroed in tail)
__device__ int    d_ptr[NN + 1];           // CSR row pointers (by dst)
__device__ int    d_pos[NN];               // fill cursors
__device__ int2   d_csr[EE + NN];          // {src, bitcast(norm)}; self incl.
__device__ float  d_ssum[2];               // scalar sum / sumsq (layer 1)
__device__ float  d_fsum[3][FF];           // per-feature sums, layers 2..4
__device__ float  d_fsq[3][FF];
__device__ float  d_pooled[GG * FF];
__device__ float  d_cnt[GG];

// ---------------- setup ------------------------------------------------------
__global__ void k_count(const int* __restrict__ ei, int E_) {
    int e = blockIdx.x * blockDim.x + threadIdx.x;
    if (e < E_) atomicAdd(&d_cnt_in[ei[E_ + e]], 1);
}

// single-block exclusive scan of (cnt_in+1) -> d_ptr
__global__ void k_scan() {
    __shared__ int sums[1024];
    int t = threadIdx.x;
    const int CH = (NN + 1023) / 1024;   // 49
    int start = t * CH;
    int end = start + CH; if (end > NN) end = NN;
    int s = 0;
    for (int i = start; i < end; i++) s += d_cnt_in[i] + 1;   // +1 self-loop
    sums[t] = s;
    __syncthreads();
    for (int off = 1; off < 1024; off <<= 1) {
        int v = (t >= off) ? sums[t - off] : 0;
        __syncthreads();
        sums[t] += v;
        __syncthreads();
    }
    int excl = (t == 0) ? 0 : sums[t - 1];
    for (int i = start; i < end; i++) {
        d_ptr[i] = excl;
        excl += d_cnt_in[i] + 1;
    }
    if (t == 1023) d_ptr[NN] = excl;
}

// parallel: dinv, self-loop CSR entry at row head, fill cursor
__global__ void k_dinvself() {
    int n = blockIdx.x * blockDim.x + threadIdx.x;
    if (n >= NN) return;
    float di = rsqrtf((float)(d_cnt_in[n] + 1));
    d_dinv[n] = di;
    int p = d_ptr[n];
    d_csr[p] = make_int2(n, __float_as_int(di * di));
    d_pos[n] = p + 1;
}

__global__ void k_fill(const int* __restrict__ ei, int E_) {
    int e = blockIdx.x * blockDim.x + threadIdx.x;
    if (e >= E_) return;
    int r = ei[e], c = ei[E_ + e];
    float nm = d_dinv[r] * d_dinv[c];
    int p = atomicAdd(&d_pos[c], 1);
    d_csr[p] = make_int2(r, __float_as_int(nm));
}

// ---------------- layer 1: scalar gather + fused stats ----------------------
__global__ void k_gather1(const float* __restrict__ x) {
    int n = blockIdx.x * blockDim.x + threadIdx.x;
    float s = 0.f;
    if (n < NN) {
        int p = d_ptr[n], en = d_ptr[n + 1];
        for (; p + 3 < en; p += 4) {
            int2 v0 = __ldg(&d_csr[p]);
            int2 v1 = __ldg(&d_csr[p + 1]);
            int2 v2 = __ldg(&d_csr[p + 2]);
            int2 v3 = __ldg(&d_csr[p + 3]);
            float x0 = __ldg(&x[v0.x]), x1 = __ldg(&x[v1.x]);
            float x2 = __ldg(&x[v2.x]), x3 = __ldg(&x[v3.x]);
            s = fmaf(x0, __int_as_float(v0.y), s);
            s = fmaf(x1, __int_as_float(v1.y), s);
            s = fmaf(x2, __int_as_float(v2.y), s);
            s = fmaf(x3, __int_as_float(v3.y), s);
        }
        for (; p < en; p++) {
            int2 v = __ldg(&d_csr[p]);
            s = fmaf(__ldg(&x[v.x]), __int_as_float(v.y), s);
        }
        d_s[n] = s;
    }
    float q = s * s;
    for (int o = 16; o; o >>= 1) {
        s += __shfl_down_sync(0xffffffffu, s, o);
        q += __shfl_down_sync(0xffffffffu, q, o);
    }
    __shared__ float sh[2][8];
    int w = threadIdx.x >> 5;
    if ((threadIdx.x & 31) == 0) { sh[0][w] = s; sh[1][w] = q; }
    __syncthreads();
    if (threadIdx.x == 0) {
        s = 0.f; q = 0.f;
        for (int i = 0; i < 8; i++) { s += sh[0][i]; q += sh[1][i]; }
        atomicAdd(&d_ssum[0], s);
        atomicAdd(&d_ssum[1], q);
    }
}

// ---------------- GEMM: d_h = (half) relu(affine(src)) @ W ------------------
template <bool FROM_S>
__global__ void k_gemm(int L, const float* __restrict__ W,
                       const float* __restrict__ Wp,   // W1 (FROM_S only)
                       const float* __restrict__ g, const float* __restrict__ bt) {
    __shared__ float Zs[FF][FF + 1];   // [k][localrow]; reused as output stage
    __shared__ float Ws[FF][FF];       // [k][col]
    __shared__ float sa[FF], sc[FF];
    int t = threadIdx.x;
    int base = blockIdx.x * FF;

    if (t < FF) {
        float inv_n = 1.0f / (float)NN;
        if (FROM_S) {
            float ms = d_ssum[0] * inv_n;
            float vs = d_ssum[1] * inv_n - ms * ms;
            float w1 = Wp[t];
            float ia = g[t] * rsqrtf(vs * w1 * w1 + BN_EPS);
            float A = ia * w1;
            sa[t] = A;
            sc[t] = bt[t] - A * ms;
        } else {
            float m = d_fsum[L][t] * inv_n;
            float v = d_fsq[L][t] * inv_n - m * m;
            float ia = g[t] * rsqrtf(v + BN_EPS);
            sa[t] = ia;
            sc[t] = bt[t] - ia * m;
        }
    }
    {
        const float4* W4 = (const float4*)W;
        float4* Ws4 = (float4*)&Ws[0][0];
        #pragma unroll
        for (int i = 0; i < 4; i++) Ws4[t + i * 256] = W4[t + i * 256];
    }
    __syncthreads();

    int lr = t >> 2;
    int cg = (t & 3) * 4;
    int row = base + lr;
    if (FROM_S) {
        float sval = (row < NN) ? d_s[row] : 0.f;
        #pragma unroll
        for (int i = 0; i < 4; i++) {
            int cc = cg + i * 16;
            #pragma unroll
            for (int j = 0; j < 4; j++)
                Zs[cc + j][lr] = fmaxf(sa[cc + j] * sval + sc[cc + j], 0.f);
        }
    } else {
        #pragma unroll
        for (int i = 0; i < 4; i++) {
            int cc = cg + i * 16;
            float4 v = (row < NN) ? *(const float4*)(d_y + (size_t)row * FF + cc)
                                  : make_float4(0.f, 0.f, 0.f, 0.f);
            Zs[cc + 0][lr] = fmaxf(sa[cc + 0] * v.x + sc[cc + 0], 0.f);
            Zs[cc + 1][lr] = fmaxf(sa[cc + 1] * v.y + sc[cc + 1], 0.f);
            Zs[cc + 2][lr] = fmaxf(sa[cc + 2] * v.z + sc[cc + 2], 0.f);
            Zs[cc + 3][lr] = fmaxf(sa[cc + 3] * v.w + sc[cc + 3], 0.f);
        }
    }
    __syncthreads();

    int tx = t & 15, ty = t >> 4;
    float acc[4][4] = {};
    #pragma unroll 16
    for (int k = 0; k < FF; k++) {
        float zr[4], wc[4];
        #pragma unroll
        for (int r = 0; r < 4; r++) zr[r] = Zs[k][ty + 16 * r];
        #pragma unroll
        for (int j = 0; j < 4; j++) wc[j] = Ws[k][tx + 16 * j];
        #pragma unroll
        for (int r = 0; r < 4; r++)
            #pragma unroll
            for (int j = 0; j < 4; j++)
                acc[r][j] = fmaf(zr[r], wc[j], acc[r][j]);
    }
    __syncthreads();    // all reads of Zs done; safe to overwrite

    // stage result into Zs[row][col] (fp32), then vectorized fp16 store
    #pragma unroll
    for (int r = 0; r < 4; r++)
        #pragma unroll
        for (int j = 0; j < 4; j++)
            Zs[ty + 16 * r][tx + 16 * j] = acc[r][j];
    __syncthreads();

    {
        int orow = base + (t >> 2);
        int seg = (t & 3) * 16;                // 16 consecutive cols
        if (orow < NN) {
            const float* zr = &Zs[t >> 2][seg];
            __half2 hp[8];
            #pragma unroll
            for (int i = 0; i < 8; i++)
                hp[i] = __floats2half2_rn(zr[2 * i], zr[2 * i + 1]);
            uint4* dst = (uint4*)(d_h + (size_t)orow * FF + seg);
            dst[0] = *(uint4*)&hp[0];
            dst[1] = *(uint4*)&hp[4];
        }
    }
}

// ---------------- 64-wide gather (fp16 source): 16 threads/node --------------
// Lane fl = lane&15 owns 4 halves (features 4fl..4fl+3); one 128B line / row.
__global__ void k_gather64(int L) {
    __shared__ float4 smS[8][32];
    __shared__ float4 smQ[8][32];
    int t = threadIdx.x;
    int lane = t & 31, w = t >> 5;          // 8 warps / block
    int fl = lane & 15, sub = lane >> 4;
    float4 rS = make_float4(0.f, 0.f, 0.f, 0.f);
    float4 rQ = make_float4(0.f, 0.f, 0.f, 0.f);
    const uint2* hb = (const uint2*)d_h;    // 16 uint2 (8B) per 64-half row

    for (int n = (blockIdx.x * 8 + w) * 2 + sub; n < NN; n += gridDim.x * 16) {
        int p = d_ptr[n], en = d_ptr[n + 1];
        float4 acc = make_float4(0.f, 0.f, 0.f, 0.f);
        for (; p + 3 < en; p += 4) {
            int2 v0 = __ldg(&d_csr[p]);
            int2 v1 = __ldg(&d_csr[p + 1]);
            int2 v2 = __ldg(&d_csr[p + 2]);
            int2 v3 = __ldg(&d_csr[p + 3]);
            uint2 u0 = __ldg(hb + (size_t)v0.x * 16 + fl);
            uint2 u1 = __ldg(hb + (size_t)v1.x * 16 + fl);
            uint2 u2 = __ldg(hb + (size_t)v2.x * 16 + fl);
            uint2 u3 = __ldg(hb + (size_t)v3.x * 16 + fl);
            float m0 = __int_as_float(v0.y), m1 = __int_as_float(v1.y);
            float m2 = __int_as_float(v2.y), m3 = __int_as_float(v3.y);
            float2 a0 = __half22float2(*(__half2*)&u0.x), b0 = __half22float2(*(__half2*)&u0.y);
            float2 a1 = __half22float2(*(__half2*)&u1.x), b1 = __half22float2(*(__half2*)&u1.y);
            float2 a2 = __half22float2(*(__half2*)&u2.x), b2 = __half22float2(*(__half2*)&u2.y);
            float2 a3 = __half22float2(*(__half2*)&u3.x), b3 = __half22float2(*(__half2*)&u3.y);
            acc.x = fmaf(a0.x, m0, acc.x); acc.y = fmaf(a0.y, m0, acc.y);
            acc.z = fmaf(b0.x, m0, acc.z); acc.w = fmaf(b0.y, m0, acc.w);
            acc.x = fmaf(a1.x, m1, acc.x); acc.y = fmaf(a1.y, m1, acc.y);
            acc.z = fmaf(b1.x, m1, acc.z); acc.w = fmaf(b1.y, m1, acc.w);
            acc.x = fmaf(a2.x, m2, acc.x); acc.y = fmaf(a2.y, m2, acc.y);
            acc.z = fmaf(b2.x, m2, acc.z); acc.w = fmaf(b2.y, m2, acc.w);
            acc.x = fmaf(a3.x, m3, acc.x); acc.y = fmaf(a3.y, m3, acc.y);
            acc.z = fmaf(b3.x, m3, acc.z); acc.w = fmaf(b3.y, m3, acc.w);
        }
        for (; p < en; p++) {
            int2 v = __ldg(&d_csr[p]);
            uint2 u0 = __ldg(hb + (size_t)v.x * 16 + fl);
            float m0 = __int_as_float(v.y);
            float2 a0 = __half22float2(*(__half2*)&u0.x), b0 = __half22float2(*(__half2*)&u0.y);
            acc.x = fmaf(a0.x, m0, acc.x); acc.y = fmaf(a0.y, m0, acc.y);
            acc.z = fmaf(b0.x, m0, acc.z); acc.w = fmaf(b0.y, m0, acc.w);
        }
        ((float4*)(d_y + (size_t)n * FF))[fl] = acc;
        rS.x += acc.x; rS.y += acc.y; rS.z += acc.z; rS.w += acc.w;
        rQ.x = fmaf(acc.x, acc.x, rQ.x); rQ.y = fmaf(acc.y, acc.y, rQ.y);
        rQ.z = fmaf(acc.z, acc.z, rQ.z); rQ.w = fmaf(acc.w, acc.w, rQ.w);
    }
    smS[w][lane] = rS; smQ[w][lane] = rQ;
    __syncthreads();
    if (t < 32) {
        float4 s = make_float4(0.f, 0.f, 0.f, 0.f);
        float4 q = make_float4(0.f, 0.f, 0.f, 0.f);
        #pragma unroll
        for (int i = 0; i < 8; i++) {
            float4 a = smS[i][t], b = smQ[i][t];
            s.x += a.x; s.y += a.y; s.z += a.z; s.w += a.w;
            q.x += b.x; q.y += b.y; q.z += b.z; q.w += b.w;
        }
        s.x += __shfl_down_sync(0xffffffffu, s.x, 16);
        s.y += __shfl_down_sync(0xffffffffu, s.y, 16);
        s.z += __shfl_down_sync(0xffffffffu, s.z, 16);
        s.w += __shfl_down_sync(0xffffffffu, s.w, 16);
        q.x += __shfl_down_sync(0xffffffffu, q.x, 16);
        q.y += __shfl_down_sync(0xffffffffu, q.y, 16);
        q.z += __shfl_down_sync(0xffffffffu, q.z, 16);
        q.w += __shfl_down_sync(0xffffffffu, q.w, 16);
        if (t < 16) {
            atomicAdd(&d_fsum[L][4 * t + 0], s.x);
            atomicAdd(&d_fsum[L][4 * t + 1], s.y);
            atomicAdd(&d_fsum[L][4 * t + 2], s.z);
            atomicAdd(&d_fsum[L][4 * t + 3], s.w);
            atomicAdd(&d_fsq[L][4 * t + 0], q.x);
            atomicAdd(&d_fsq[L][4 * t + 1], q.y);
            atomicAdd(&d_fsq[L][4 * t + 2], q.z);
            atomicAdd(&d_fsq[L][4 * t + 3], q.w);
        }
    }
}

// ---------------- pooling (BN4+ReLU inline) ----------------------------------
__global__ void k_pool(const int* __restrict__ batch,
                       const float* __restrict__ g4, const float* __restrict__ bt4) {
    int t = threadIdx.x;
    int f = t & 63, rg = t >> 6;
    int base = blockIdx.x * 256;
    float inv_n = 1.0f / (float)NN;
    float m = d_fsum[2][f] * inv_n;
    float v = d_fsq[2][f] * inv_n - m * m;
    float ia = g4[f] * rsqrtf(v + BN_EPS);
    float af = ia, cf = bt4[f] - ia * m;
    float acc = 0.f, cacc = 0.f;
    int gcur = -1;
    for (int i = 0; i < 64; i++) {
        int n = base + rg + 4 * i;
        if (n >= NN) break;
        int g = batch[n];
        if (g != gcur) {
            if (gcur >= 0) {
                atomicAdd(&d_pooled[gcur * FF + f], acc);
                if (f == 0) atomicAdd(&d_cnt[gcur], cacc);
            }
            gcur = g; acc = 0.f; cacc = 0.f;
        }
        float vv = fmaxf(af * d_y[(size_t)n * FF + f] + cf, 0.f);
        acc += vv; cacc += 1.f;
    }
    if (gcur >= 0) {
        atomicAdd(&d_pooled[gcur * FF + f], acc);
        if (f == 0) atomicAdd(&d_cnt[gcur], cacc);
    }
}

// ---------------- MLP head: one block per graph, transposed fw1 in smem ------
__global__ void k_fc(const float* __restrict__ fw1, const float* __restrict__ fb1,
                     const float* __restrict__ fw2, const float* __restrict__ fb2,
                     float* __restrict__ out) {
    __shared__ float FWt[FF][129];
    __shared__ float P[FF];
    __shared__ float H[128];
    int t = threadIdx.x;               // 128 threads
    int g = blockIdx.x;                // 64 blocks

    for (int idx = t; idx < 128 * FF; idx += 128) {
        int j = idx >> 6, f = idx & 63;
        FWt[f][j] = fw1[idx];
    }
    if (t < FF) {
        float cc = d_cnt[g]; cc = (cc < 1.f) ? 1.f : cc;
        P[t] = d_pooled[g * FF + t] / cc;
    }
    __syncthreads();

    {
        float s = fb1[t];
        #pragma unroll 16
        for (int f = 0; f < FF; f++) s = fmaf(P[f], FWt[f][t], s);
        H[t] = fmaxf(s, 0.f);
    }
    __syncthreads();

    if (t < 10) {
        float s = fb2[t];
        #pragma unroll 16
        for (int j = 0; j < 128; j++) s = fmaf(H[j], fw2[t * 128 + j], s);
        out[g * 10 + t] = s;
    }

    // ---- tail-zero for next call
    if (t < FF) d_pooled[g * FF + t] = 0.f;
    if (t == 0) d_cnt[g] = 0.f;
    for (int i = g * 128 + t; i < NN; i += GG * 128) d_cnt_in[i] = 0;
    if (g == 0) {
        if (t < 2) d_ssum[t] = 0.f;
        if (t < 128) {
            ((float*)d_fsum)[t] = 0.f; ((float*)d_fsum)[t + 64] = 0.f;
            ((float*)d_fsq)[t]  = 0.f; ((float*)d_fsq)[t + 64]  = 0.f;
        }
        if (t < 64) { ((float*)d_fsum)[128 + t] = 0.f; ((float*)d_fsq)[128 + t] = 0.f; }
    }
}

// ---------------- launch -----------------------------------------------------
extern "C" void kernel_launch(void* const* d_in, const int* in_sizes, int n_in,
                              void* d_out, int out_size) {
    const float* x   = (const float*)d_in[0];
    const int*   ei  = (const int*)d_in[1];
    const int*   bat = (const int*)d_in[2];
    const float* W1  = (const float*)d_in[3];
    const float* g1  = (const float*)d_in[5];
    const float* bt1 = (const float*)d_in[6];
    const float* W2  = (const float*)d_in[7];
    const float* g2  = (const float*)d_in[9];
    const float* bt2 = (const float*)d_in[10];
    const float* W3  = (const float*)d_in[11];
    const float* g3  = (const float*)d_in[13];
    const float* bt3 = (const float*)d_in[14];
    const float* W4  = (const float*)d_in[15];
    const float* g4  = (const float*)d_in[17];
    const float* bt4 = (const float*)d_in[18];
    const float* fw1 = (const float*)d_in[19];
    const float* fb1 = (const float*)d_in[20];
    const float* fw2 = (const float*)d_in[21];
    const float* fb2 = (const float*)d_in[22];
    float* out = (float*)d_out;

    int E_ = in_sizes[1] / 2;
    if (E_ > EE) E_ = EE;

    const int TB = 256;
    int nb_n = (NN + TB - 1) / TB;
    int nb_e = (E_ + TB - 1) / TB;
    int nb_g = (NN + 63) / 64;
    const int GATHER_BLKS = 592;

    // CSR build (self-loops embedded)
    k_count<<<nb_e, TB>>>(ei, E_);
    k_scan<<<1, 1024>>>();
    k_dinvself<<<nb_n, TB>>>();
    k_fill<<<nb_e, TB>>>(ei, E_);

    // layer 1 (scalar)
    k_gather1<<<nb_n, TB>>>(x);

    // layer 2
    k_gemm<true><<<nb_g, TB>>>(0, W2, W1, g1, bt1);
    k_gather64<<<GATHER_BLKS, TB>>>(0);

    // layer 3
    k_gemm<false><<<nb_g, TB>>>(0, W3, nullptr, g2, bt2);
    k_gather64<<<GATHER_BLKS, TB>>>(1);

    // layer 4
    k_gemm<false><<<nb_g, TB>>>(1, W4, nullptr, g3, bt3);
    k_gather64<<<GATHER_BLKS, TB>>>(2);

    // pool + head (+ tail-zero)
    k_pool<<<(NN + 255) / 256, TB>>>(bat, g4, bt4);
    k_fc<<<GG, 128>>>(fw1, fb1, fw2, fb2, out);
}